// round 10
// baseline (speedup 1.0000x reference)
#include <cuda_runtime.h>
#include <math.h>

#define NMAX 100000
#define EMAX 3200000
#define F_IN 128
#define HID  16
#define NC   10
#define CP   16   // layer-2 width padded to 16 so both layers share gather16

// ---- scratch (static device globals; no allocation allowed) ----
__device__ float g_g1  [NMAX * HID];  // (x@W1) * dinv[src-side]
__device__ float g_tmp1[NMAX * HID];  // gathered sums layer 1
__device__ float g_g2  [NMAX * CP];   // (h@W2) * dinv, padded to 16
__device__ float g_tmp2[NMAX * CP];   // gathered sums layer 2
__device__ float g_dinv[NMAX];
__device__ int   g_cnt [NMAX];        // in-degree (dst counts)
__device__ int   g_cnt2[NMAX];        // placement cursors
__device__ int   g_base[NMAX];        // CSR row offsets (by dst)
__device__ int   g_bsum[512];         // block sums for scan
__device__ int   g_csr [EMAX];        // src indices grouped by dst

// ---------------------------------------------------------------
__global__ void zero_kernel(int n) {
    int i = blockIdx.x * blockDim.x + threadIdx.x;
    if (i < n) { g_cnt[i] = 0; g_cnt2[i] = 0; }
}

__global__ void deg_kernel(const int* __restrict__ dst, int e) {
    int i = blockIdx.x * blockDim.x + threadIdx.x;
    if (i < e) atomicAdd(&g_cnt[dst[i]], 1);
}

// ---- scan stage 1 (+ fused dinv): per-block sums of g_cnt ----
__global__ __launch_bounds__(256) void scan1_kernel(int n) {
    __shared__ int wsum[8];
    int i = blockIdx.x * 256 + threadIdx.x;
    int lane = threadIdx.x & 31, warp = threadIdx.x >> 5;
    int v = (i < n) ? g_cnt[i] : 0;
    if (i < n) g_dinv[i] = rsqrtf((float)v + 1.0f);   // fused dinv
    int s = v;
#pragma unroll
    for (int d = 16; d > 0; d >>= 1) s += __shfl_down_sync(~0u, s, d);
    if (lane == 0) wsum[warp] = s;
    __syncthreads();
    if (threadIdx.x == 0) {
        int t = 0;
#pragma unroll
        for (int w = 0; w < 8; ++w) t += wsum[w];
        g_bsum[blockIdx.x] = t;
    }
}

// ---- scan stage 2+3 fused: each block reduces g_bsum[0..bid) itself,
// then does the intra-block exclusive scan -> g_base ----
__global__ __launch_bounds__(256) void scan3_kernel(int n) {
    __shared__ int wsum[8];
    __shared__ int wred[8];
    __shared__ int s_boff;
    int lane = threadIdx.x & 31, warp = threadIdx.x >> 5;

    // block offset = sum of g_bsum[0..blockIdx.x)
    int partial = 0;
    for (int j = threadIdx.x; j < blockIdx.x; j += 256) partial += g_bsum[j];
#pragma unroll
    for (int d = 16; d > 0; d >>= 1) partial += __shfl_down_sync(~0u, partial, d);
    if (lane == 0) wred[warp] = partial;
    __syncthreads();
    if (threadIdx.x == 0) {
        int t = 0;
#pragma unroll
        for (int w = 0; w < 8; ++w) t += wred[w];
        s_boff = t;
    }

    // intra-block inclusive scan of g_cnt
    int i = blockIdx.x * 256 + threadIdx.x;
    int orig = (i < n) ? g_cnt[i] : 0;
    int v = orig;
#pragma unroll
    for (int d = 1; d < 32; d <<= 1) {
        int t = __shfl_up_sync(~0u, v, d);
        if (lane >= d) v += t;
    }
    if (lane == 31) wsum[warp] = v;
    __syncthreads();
    if (warp == 0 && lane < 8) {
        int s = wsum[lane];
#pragma unroll
        for (int d = 1; d < 8; d <<= 1) {
            int t = __shfl_up_sync(0xffu, s, d);
            if (lane >= d) s += t;
        }
        wsum[lane] = s;
    }
    __syncthreads();
    int wbase = (warp > 0) ? wsum[warp - 1] : 0;
    if (i < n) g_base[i] = s_boff + wbase + v - orig;
}

// ---- CSR placement: group src indices by dst ----
__global__ void place_kernel(const int* __restrict__ src,
                             const int* __restrict__ dst, int e) {
    int i = blockIdx.x * blockDim.x + threadIdx.x;
    if (i >= e) return;
    int d = dst[i];
    int pos = g_base[d] + atomicAdd(&g_cnt2[d], 1);
    g_csr[pos] = src[i];
}

// ---- GEMM1 v3: g1 = (x @ W1) * dinv.  Block=128 threads, 256 rows/block.
// Stage 256x32 chunk in smem (pad 36 -> 16B-aligned, conflict-free float4
// reads); each thread computes 2 rows so weight LDS amortizes 2x. ----
__global__ __launch_bounds__(128) void gemm1_kernel(const float* __restrict__ x,
                                                    const float* __restrict__ W1,
                                                    int n) {
    __shared__ float w1s[F_IN * HID];      // 8 KB  [k][o]
    __shared__ float xs[256][36];          // 36 KB, padded
    const int tid = threadIdx.x;
    const int row0 = blockIdx.x * 256;

#pragma unroll
    for (int i = tid; i < F_IN * HID; i += 128)
        w1s[i] = W1[i];

    float acc0[16], acc1[16];
#pragma unroll
    for (int o = 0; o < 16; ++o) { acc0[o] = 0.f; acc1[o] = 0.f; }

#pragma unroll 1
    for (int kc = 0; kc < 4; ++kc) {
        __syncthreads();   // xs reuse from previous chunk
        // coalesced stage of 256 rows x 32 k
#pragma unroll 8
        for (int i = tid; i < 256 * 32; i += 128) {
            int r = i >> 5, k = i & 31;
            int row = row0 + r;
            xs[r][k] = (row < n) ? x[(size_t)row * F_IN + kc * 32 + k] : 0.f;
        }
        __syncthreads();

#pragma unroll
        for (int k4 = 0; k4 < 8; ++k4) {
            float4 xa = *(const float4*)&xs[tid][k4 * 4];
            float4 xb = *(const float4*)&xs[tid + 128][k4 * 4];
            const float* wbase = w1s + (kc * 32 + k4 * 4) * HID;
#pragma unroll
            for (int kk = 0; kk < 4; ++kk) {
                float va = (kk == 0) ? xa.x : (kk == 1) ? xa.y : (kk == 2) ? xa.z : xa.w;
                float vb = (kk == 0) ? xb.x : (kk == 1) ? xb.y : (kk == 2) ? xb.z : xb.w;
                const float* w = wbase + kk * HID;
                float4 w0 = *(const float4*)(w + 0);
                float4 w1 = *(const float4*)(w + 4);
                float4 w2 = *(const float4*)(w + 8);
                float4 w3 = *(const float4*)(w + 12);
                acc0[0]  = fmaf(va, w0.x, acc0[0]);  acc1[0]  = fmaf(vb, w0.x, acc1[0]);
                acc0[1]  = fmaf(va, w0.y, acc0[1]);  acc1[1]  = fmaf(vb, w0.y, acc1[1]);
                acc0[2]  = fmaf(va, w0.z, acc0[2]);  acc1[2]  = fmaf(vb, w0.z, acc1[2]);
                acc0[3]  = fmaf(va, w0.w, acc0[3]);  acc1[3]  = fmaf(vb, w0.w, acc1[3]);
                acc0[4]  = fmaf(va, w1.x, acc0[4]);  acc1[4]  = fmaf(vb, w1.x, acc1[4]);
                acc0[5]  = fmaf(va, w1.y, acc0[5]);  acc1[5]  = fmaf(vb, w1.y, acc1[5]);
                acc0[6]  = fmaf(va, w1.z, acc0[6]);  acc1[6]  = fmaf(vb, w1.z, acc1[6]);
                acc0[7]  = fmaf(va, w1.w, acc0[7]);  acc1[7]  = fmaf(vb, w1.w, acc1[7]);
                acc0[8]  = fmaf(va, w2.x, acc0[8]);  acc1[8]  = fmaf(vb, w2.x, acc1[8]);
                acc0[9]  = fmaf(va, w2.y, acc0[9]);  acc1[9]  = fmaf(vb, w2.y, acc1[9]);
                acc0[10] = fmaf(va, w2.z, acc0[10]); acc1[10] = fmaf(vb, w2.z, acc1[10]);
                acc0[11] = fmaf(va, w2.w, acc0[11]); acc1[11] = fmaf(vb, w2.w, acc1[11]);
                acc0[12] = fmaf(va, w3.x, acc0[12]); acc1[12] = fmaf(vb, w3.x, acc1[12]);
                acc0[13] = fmaf(va, w3.y, acc0[13]); acc1[13] = fmaf(vb, w3.y, acc1[13]);
                acc0[14] = fmaf(va, w3.z, acc0[14]); acc1[14] = fmaf(vb, w3.z, acc1[14]);
                acc0[15] = fmaf(va, w3.w, acc0[15]); acc1[15] = fmaf(vb, w3.w, acc1[15]);
            }
        }
    }

    int rowA = row0 + tid, rowB = row0 + tid + 128;
    if (rowA < n) {
        float dv = g_dinv[rowA];
        float* out = g_g1 + (size_t)rowA * HID;
#pragma unroll
        for (int o = 0; o < 16; o += 4)
            *(float4*)(out + o) = make_float4(acc0[o] * dv, acc0[o + 1] * dv,
                                              acc0[o + 2] * dv, acc0[o + 3] * dv);
    }
    if (rowB < n) {
        float dv = g_dinv[rowB];
        float* out = g_g1 + (size_t)rowB * HID;
#pragma unroll
        for (int o = 0; o < 16; o += 4)
            *(float4*)(out + o) = make_float4(acc1[o] * dv, acc1[o + 1] * dv,
                                              acc1[o + 2] * dv, acc1[o + 3] * dv);
    }
}

// ---- gather: out[v] = sum over incoming edges of in[src], 16 floats wide.
// One warp per node; 4 lanes per edge, 8 edges per iteration; butterfly
// reduce; lanes 0-3 write. LAYER selects device-global arrays in device code.
template <int LAYER>
__global__ __launch_bounds__(256) void gather16_kernel(int n) {
    const float* __restrict__ in = (LAYER == 0) ? g_g1 : g_g2;
    float* __restrict__ out      = (LAYER == 0) ? g_tmp1 : g_tmp2;

    int gw = (blockIdx.x * 256 + threadIdx.x) >> 5;
    if (gw >= n) return;
    int lane = threadIdx.x & 31;
    int eq = lane >> 2, q = lane & 3;
    int start = g_base[gw];
    int m = g_cnt[gw];
    const int* cs = g_csr + start;

    float4 acc = make_float4(0.f, 0.f, 0.f, 0.f);
    int j = eq;
    for (; j + 8 < m; j += 16) {
        int s0 = cs[j], s1 = cs[j + 8];
        float4 a = *(const float4*)(in + (size_t)s0 * 16 + q * 4);
        float4 b = *(const float4*)(in + (size_t)s1 * 16 + q * 4);
        acc.x += a.x + b.x; acc.y += a.y + b.y;
        acc.z += a.z + b.z; acc.w += a.w + b.w;
    }
    for (; j < m; j += 8) {
        int s = cs[j];
        float4 a = *(const float4*)(in + (size_t)s * 16 + q * 4);
        acc.x += a.x; acc.y += a.y; acc.z += a.z; acc.w += a.w;
    }
#pragma unroll
    for (int st = 4; st < 32; st <<= 1) {
        acc.x += __shfl_xor_sync(~0u, acc.x, st);
        acc.y += __shfl_xor_sync(~0u, acc.y, st);
        acc.z += __shfl_xor_sync(~0u, acc.z, st);
        acc.w += __shfl_xor_sync(~0u, acc.w, st);
    }
    if (lane < 4)
        *(float4*)(out + (size_t)gw * 16 + q * 4) = acc;
}

// ---- finalize layer1 + GEMM2: h=relu(dinv*(tmp1+g1)+b1); g2=(h@W2)*dinv ----
__global__ __launch_bounds__(256) void fin1_kernel(const float* __restrict__ b1,
                                                   const float* __restrict__ W2,
                                                   int n) {
    __shared__ float w2s[HID * NC];
    __shared__ float b1s[HID];
    int tid = threadIdx.x;
    if (tid < HID * NC) w2s[tid] = W2[tid];
    if (tid < HID)      b1s[tid] = b1[tid];
    __syncthreads();

    int i = blockIdx.x * 256 + tid;
    if (i >= n) return;
    float dv = g_dinv[i];

    float h[16];
    const float4* tp = (const float4*)(g_tmp1 + (size_t)i * HID);
    const float4* gp = (const float4*)(g_g1 + (size_t)i * HID);
#pragma unroll
    for (int o4 = 0; o4 < 4; ++o4) {
        float4 t = tp[o4], g = gp[o4];
        h[o4 * 4 + 0] = fmaxf(fmaf(dv, t.x + g.x, b1s[o4 * 4 + 0]), 0.f);
        h[o4 * 4 + 1] = fmaxf(fmaf(dv, t.y + g.y, b1s[o4 * 4 + 1]), 0.f);
        h[o4 * 4 + 2] = fmaxf(fmaf(dv, t.z + g.z, b1s[o4 * 4 + 2]), 0.f);
        h[o4 * 4 + 3] = fmaxf(fmaf(dv, t.w + g.w, b1s[o4 * 4 + 3]), 0.f);
    }

    float acc[NC];
#pragma unroll
    for (int c = 0; c < NC; ++c) acc[c] = 0.f;
#pragma unroll
    for (int o = 0; o < HID; ++o) {
        float hv = h[o];
#pragma unroll
        for (int c = 0; c < NC; ++c) acc[c] = fmaf(hv, w2s[o * NC + c], acc[c]);
    }

    float* out = g_g2 + (size_t)i * CP;
    ((float4*)out)[0] = make_float4(acc[0] * dv, acc[1] * dv, acc[2] * dv, acc[3] * dv);
    ((float4*)out)[1] = make_float4(acc[4] * dv, acc[5] * dv, acc[6] * dv, acc[7] * dv);
    ((float4*)out)[2] = make_float4(acc[8] * dv, acc[9] * dv, 0.f, 0.f);
    ((float4*)out)[3] = make_float4(0.f, 0.f, 0.f, 0.f);
}

// ---- finalize layer2 + softmax ----
__global__ __launch_bounds__(256) void fin2_kernel(const float* __restrict__ b2,
                                                   float* __restrict__ out, int n) {
    __shared__ float b2s[NC];
    if (threadIdx.x < NC) b2s[threadIdx.x] = b2[threadIdx.x];
    __syncthreads();
    int i = blockIdx.x * blockDim.x + threadIdx.x;
    if (i >= n) return;
    float dv = g_dinv[i];
    const float* tp = g_tmp2 + (size_t)i * CP;
    const float* gp = g_g2 + (size_t)i * CP;
    float l[NC];
    float m = -1e30f;
#pragma unroll
    for (int c = 0; c < NC; ++c) {
        l[c] = fmaf(dv, tp[c] + gp[c], b2s[c]);
        m = fmaxf(m, l[c]);
    }
    float sum = 0.f;
#pragma unroll
    for (int c = 0; c < NC; ++c) {
        l[c] = expf(l[c] - m);
        sum += l[c];
    }
    float inv = 1.0f / sum;
#pragma unroll
    for (int c = 0; c < NC; ++c) out[i * NC + c] = l[c] * inv;
}

// ---------------------------------------------------------------
extern "C" void kernel_launch(void* const* d_in, const int* in_sizes, int n_in,
                              void* d_out, int out_size) {
    const float* x  = (const float*)d_in[0];
    const int*   ei = (const int*)  d_in[1];
    const float* W1 = (const float*)d_in[2];
    const float* b1 = (const float*)d_in[3];
    const float* W2 = (const float*)d_in[4];
    const float* b2 = (const float*)d_in[5];
    float* out = (float*)d_out;

    int n = in_sizes[0] / F_IN;
    int e = in_sizes[1] / 2;
    const int* src = ei;
    const int* dst = ei + e;
    int nb = (n + 255) / 256;   // <=512 (g_bsum capacity)

    zero_kernel <<<nb, 256>>>(n);
    deg_kernel  <<<(e + 255) / 256, 256>>>(dst, e);
    scan1_kernel<<<nb, 256>>>(n);
    scan3_kernel<<<nb, 256>>>(n);
    place_kernel<<<(e + 255) / 256, 256>>>(src, dst, e);
    gemm1_kernel<<<nb, 128>>>(x, W1, n);
    gather16_kernel<0><<<(n * 32 + 255) / 256, 256>>>(n);
    fin1_kernel <<<nb, 256>>>(b1, W2, n);
    gather16_kernel<1><<<(n * 32 + 255) / 256, 256>>>(n);
    fin2_kernel <<<nb, 256>>>(b2, out, n);
}

// round 11
// speedup vs baseline: 1.0866x; 1.0866x over previous
#include <cuda_runtime.h>
#include <math.h>

#define NMAX 100000
#define EMAX 3200000
#define F_IN 128
#define HID  16
#define NC   10
#define CP   12   // layer-2 row stride: 12 floats = 48B, float4-aligned

// ---- scratch (static device globals; no allocation allowed) ----
__device__ float g_g1  [NMAX * HID];  // (x@W1) * dinv[src-side]
__device__ float g_tmp1[NMAX * HID];  // gathered sums layer 1
__device__ float g_g2  [NMAX * CP];   // (h@W2) * dinv, padded to 12
__device__ float g_tmp2[NMAX * CP];   // gathered sums layer 2
__device__ float g_dinv[NMAX];
__device__ int   g_cnt [NMAX];        // in-degree (dst counts)
__device__ int   g_cnt2[NMAX];        // placement cursors
__device__ int   g_base[NMAX];        // CSR row offsets (by dst)
__device__ int   g_bsum[512];         // block sums for scan
__device__ int   g_csr [EMAX];        // src indices grouped by dst

// ---------------------------------------------------------------
__global__ void zero_kernel(int n) {
    int i = blockIdx.x * blockDim.x + threadIdx.x;
    if (i < n) { g_cnt[i] = 0; g_cnt2[i] = 0; }
}

__global__ void deg_kernel(const int* __restrict__ dst, int e) {
    int i = blockIdx.x * blockDim.x + threadIdx.x;
    if (i < e) atomicAdd(&g_cnt[dst[i]], 1);
}

// ---- scan stage 1 (+ fused dinv): per-block sums of g_cnt ----
__global__ __launch_bounds__(256) void scan1_kernel(int n) {
    __shared__ int wsum[8];
    int i = blockIdx.x * 256 + threadIdx.x;
    int lane = threadIdx.x & 31, warp = threadIdx.x >> 5;
    int v = (i < n) ? g_cnt[i] : 0;
    if (i < n) g_dinv[i] = rsqrtf((float)v + 1.0f);   // fused dinv
    int s = v;
#pragma unroll
    for (int d = 16; d > 0; d >>= 1) s += __shfl_down_sync(~0u, s, d);
    if (lane == 0) wsum[warp] = s;
    __syncthreads();
    if (threadIdx.x == 0) {
        int t = 0;
#pragma unroll
        for (int w = 0; w < 8; ++w) t += wsum[w];
        g_bsum[blockIdx.x] = t;
    }
}

// ---- scan stage 2+3 fused: block offset from g_bsum prefix, then
// intra-block exclusive scan -> g_base ----
__global__ __launch_bounds__(256) void scan3_kernel(int n) {
    __shared__ int wsum[8];
    __shared__ int wred[8];
    __shared__ int s_boff;
    int lane = threadIdx.x & 31, warp = threadIdx.x >> 5;

    int partial = 0;
    for (int j = threadIdx.x; j < blockIdx.x; j += 256) partial += g_bsum[j];
#pragma unroll
    for (int d = 16; d > 0; d >>= 1) partial += __shfl_down_sync(~0u, partial, d);
    if (lane == 0) wred[warp] = partial;
    __syncthreads();
    if (threadIdx.x == 0) {
        int t = 0;
#pragma unroll
        for (int w = 0; w < 8; ++w) t += wred[w];
        s_boff = t;
    }

    int i = blockIdx.x * 256 + threadIdx.x;
    int orig = (i < n) ? g_cnt[i] : 0;
    int v = orig;
#pragma unroll
    for (int d = 1; d < 32; d <<= 1) {
        int t = __shfl_up_sync(~0u, v, d);
        if (lane >= d) v += t;
    }
    if (lane == 31) wsum[warp] = v;
    __syncthreads();
    if (warp == 0 && lane < 8) {
        int s = wsum[lane];
#pragma unroll
        for (int d = 1; d < 8; d <<= 1) {
            int t = __shfl_up_sync(0xffu, s, d);
            if (lane >= d) s += t;
        }
        wsum[lane] = s;
    }
    __syncthreads();
    int wbase = (warp > 0) ? wsum[warp - 1] : 0;
    if (i < n) g_base[i] = s_boff + wbase + v - orig;
}

// ---- CSR placement: group src indices by dst ----
__global__ void place_kernel(const int* __restrict__ src,
                             const int* __restrict__ dst, int e) {
    int i = blockIdx.x * blockDim.x + threadIdx.x;
    if (i >= e) return;
    int d = dst[i];
    int pos = g_base[d] + atomicAdd(&g_cnt2[d], 1);
    g_csr[pos] = src[i];
}

// ---- GEMM1: g1 = (x @ W1) * dinv (warp-staged; measured-good r5 version) ----
__global__ __launch_bounds__(256) void gemm1_kernel(const float* __restrict__ x,
                                                    const float* __restrict__ W1,
                                                    int n) {
    __shared__ float w1s[F_IN * HID];
    __shared__ float xs[8][32][33];
#pragma unroll
    for (int i = threadIdx.x; i < F_IN * HID; i += 256)
        w1s[i] = W1[i];
    __syncthreads();

    const int warp = threadIdx.x >> 5;
    const int lane = threadIdx.x & 31;
    const int row0 = blockIdx.x * 256 + warp * 32;
    const int myrow = row0 + lane;

    float acc[16];
#pragma unroll
    for (int o = 0; o < 16; ++o) acc[o] = 0.f;

#pragma unroll 1
    for (int kc = 0; kc < 4; ++kc) {
#pragma unroll 8
        for (int r = 0; r < 32; ++r) {
            int row = row0 + r;
            xs[warp][r][lane] = (row < n)
                ? x[(size_t)row * F_IN + kc * 32 + lane] : 0.f;
        }
        __syncwarp();
#pragma unroll
        for (int k = 0; k < 32; ++k) {
            float xv = xs[warp][lane][k];
            const float* w = w1s + (kc * 32 + k) * HID;
            float4 wa = *(const float4*)(w + 0);
            float4 wb = *(const float4*)(w + 4);
            float4 wc = *(const float4*)(w + 8);
            float4 wd = *(const float4*)(w + 12);
            acc[0]  = fmaf(xv, wa.x, acc[0]);  acc[1]  = fmaf(xv, wa.y, acc[1]);
            acc[2]  = fmaf(xv, wa.z, acc[2]);  acc[3]  = fmaf(xv, wa.w, acc[3]);
            acc[4]  = fmaf(xv, wb.x, acc[4]);  acc[5]  = fmaf(xv, wb.y, acc[5]);
            acc[6]  = fmaf(xv, wb.z, acc[6]);  acc[7]  = fmaf(xv, wb.w, acc[7]);
            acc[8]  = fmaf(xv, wc.x, acc[8]);  acc[9]  = fmaf(xv, wc.y, acc[9]);
            acc[10] = fmaf(xv, wc.z, acc[10]); acc[11] = fmaf(xv, wc.w, acc[11]);
            acc[12] = fmaf(xv, wd.x, acc[12]); acc[13] = fmaf(xv, wd.y, acc[13]);
            acc[14] = fmaf(xv, wd.z, acc[14]); acc[15] = fmaf(xv, wd.w, acc[15]);
        }
        __syncwarp();
    }

    if (myrow < n) {
        float dv = g_dinv[myrow];
        float* out = g_g1 + (size_t)myrow * HID;
#pragma unroll
        for (int o = 0; o < 16; o += 4)
            *(float4*)(out + o) = make_float4(acc[o] * dv, acc[o + 1] * dv,
                                              acc[o + 2] * dv, acc[o + 3] * dv);
    }
}

// ---- gather: out[v] = sum of in[src] over incoming edges.
// One warp per node, 4-lane edge groups, 8 edges/iter, butterfly reduce.
// LAYER 0: 16-wide rows (stride 16). LAYER 1: 12-wide rows (stride 12),
// lane q==3 contributes zeros (no load) and does not write. ----
template <int LAYER>
__global__ __launch_bounds__(256) void gather_kernel(int n) {
    const float* __restrict__ in = (LAYER == 0) ? g_g1 : g_g2;
    float* __restrict__ out      = (LAYER == 0) ? g_tmp1 : g_tmp2;
    const int stride = (LAYER == 0) ? HID : CP;
    const int nq     = (LAYER == 0) ? 4 : 3;    // active quarters

    int gw = (blockIdx.x * 256 + threadIdx.x) >> 5;
    if (gw >= n) return;
    int lane = threadIdx.x & 31;
    int eq = lane >> 2, q = lane & 3;
    int start = g_base[gw];
    int m = g_cnt[gw];
    const int* cs = g_csr + start;

    float4 acc = make_float4(0.f, 0.f, 0.f, 0.f);
    if (q < nq) {
        int j = eq;
        for (; j + 8 < m; j += 16) {
            int s0 = cs[j], s1 = cs[j + 8];
            float4 a = *(const float4*)(in + (size_t)s0 * stride + q * 4);
            float4 b = *(const float4*)(in + (size_t)s1 * stride + q * 4);
            acc.x += a.x + b.x; acc.y += a.y + b.y;
            acc.z += a.z + b.z; acc.w += a.w + b.w;
        }
        for (; j < m; j += 8) {
            int s = cs[j];
            float4 a = *(const float4*)(in + (size_t)s * stride + q * 4);
            acc.x += a.x; acc.y += a.y; acc.z += a.z; acc.w += a.w;
        }
    }
#pragma unroll
    for (int st = 4; st < 32; st <<= 1) {
        acc.x += __shfl_xor_sync(~0u, acc.x, st);
        acc.y += __shfl_xor_sync(~0u, acc.y, st);
        acc.z += __shfl_xor_sync(~0u, acc.z, st);
        acc.w += __shfl_xor_sync(~0u, acc.w, st);
    }
    if (lane < nq)
        *(float4*)(out + (size_t)gw * stride + q * 4) = acc;
}

// ---- finalize layer1 + GEMM2: h=relu(dinv*(tmp1+g1)+b1); g2=(h@W2)*dinv ----
__global__ __launch_bounds__(256) void fin1_kernel(const float* __restrict__ b1,
                                                   const float* __restrict__ W2,
                                                   int n) {
    __shared__ float w2s[HID * NC];
    __shared__ float b1s[HID];
    int tid = threadIdx.x;
    if (tid < HID * NC) w2s[tid] = W2[tid];
    if (tid < HID)      b1s[tid] = b1[tid];
    __syncthreads();

    int i = blockIdx.x * 256 + tid;
    if (i >= n) return;
    float dv = g_dinv[i];

    float h[16];
    const float4* tp = (const float4*)(g_tmp1 + (size_t)i * HID);
    const float4* gp = (const float4*)(g_g1 + (size_t)i * HID);
#pragma unroll
    for (int o4 = 0; o4 < 4; ++o4) {
        float4 t = tp[o4], g = gp[o4];
        h[o4 * 4 + 0] = fmaxf(fmaf(dv, t.x + g.x, b1s[o4 * 4 + 0]), 0.f);
        h[o4 * 4 + 1] = fmaxf(fmaf(dv, t.y + g.y, b1s[o4 * 4 + 1]), 0.f);
        h[o4 * 4 + 2] = fmaxf(fmaf(dv, t.z + g.z, b1s[o4 * 4 + 2]), 0.f);
        h[o4 * 4 + 3] = fmaxf(fmaf(dv, t.w + g.w, b1s[o4 * 4 + 3]), 0.f);
    }

    float acc[NC];
#pragma unroll
    for (int c = 0; c < NC; ++c) acc[c] = 0.f;
#pragma unroll
    for (int o = 0; o < HID; ++o) {
        float hv = h[o];
#pragma unroll
        for (int c = 0; c < NC; ++c) acc[c] = fmaf(hv, w2s[o * NC + c], acc[c]);
    }

    float* out = g_g2 + (size_t)i * CP;
    ((float4*)out)[0] = make_float4(acc[0] * dv, acc[1] * dv, acc[2] * dv, acc[3] * dv);
    ((float4*)out)[1] = make_float4(acc[4] * dv, acc[5] * dv, acc[6] * dv, acc[7] * dv);
    ((float4*)out)[2] = make_float4(acc[8] * dv, acc[9] * dv, 0.f, 0.f);
}

// ---- finalize layer2 + softmax ----
__global__ __launch_bounds__(256) void fin2_kernel(const float* __restrict__ b2,
                                                   float* __restrict__ out, int n) {
    __shared__ float b2s[NC];
    if (threadIdx.x < NC) b2s[threadIdx.x] = b2[threadIdx.x];
    __syncthreads();
    int i = blockIdx.x * blockDim.x + threadIdx.x;
    if (i >= n) return;
    float dv = g_dinv[i];
    const float* tp = g_tmp2 + (size_t)i * CP;
    const float* gp = g_g2 + (size_t)i * CP;
    float l[NC];
    float m = -1e30f;
#pragma unroll
    for (int c = 0; c < NC; ++c) {
        l[c] = fmaf(dv, tp[c] + gp[c], b2s[c]);
        m = fmaxf(m, l[c]);
    }
    float sum = 0.f;
#pragma unroll
    for (int c = 0; c < NC; ++c) {
        l[c] = expf(l[c] - m);
        sum += l[c];
    }
    float inv = 1.0f / sum;
#pragma unroll
    for (int c = 0; c < NC; ++c) out[i * NC + c] = l[c] * inv;
}

// ---------------------------------------------------------------
extern "C" void kernel_launch(void* const* d_in, const int* in_sizes, int n_in,
                              void* d_out, int out_size) {
    const float* x  = (const float*)d_in[0];
    const int*   ei = (const int*)  d_in[1];
    const float* W1 = (const float*)d_in[2];
    const float* b1 = (const float*)d_in[3];
    const float* W2 = (const float*)d_in[4];
    const float* b2 = (const float*)d_in[5];
    float* out = (float*)d_out;

    int n = in_sizes[0] / F_IN;
    int e = in_sizes[1] / 2;
    const int* src = ei;
    const int* dst = ei + e;
    int nb = (n + 255) / 256;   // <=512 (g_bsum capacity)

    zero_kernel <<<nb, 256>>>(n);
    deg_kernel  <<<(e + 255) / 256, 256>>>(dst, e);
    scan1_kernel<<<nb, 256>>>(n);
    scan3_kernel<<<nb, 256>>>(n);
    place_kernel<<<(e + 255) / 256, 256>>>(src, dst, e);
    gemm1_kernel<<<nb, 256>>>(x, W1, n);
    gather_kernel<0><<<(n * 32 + 255) / 256, 256>>>(n);
    fin1_kernel <<<nb, 256>>>(b1, W2, n);
    gather_kernel<1><<<(n * 32 + 255) / 256, 256>>>(n);
    fin2_kernel <<<nb, 256>>>(b2, out, n);
}